// round 13
// baseline (speedup 1.0000x reference)
#include <cuda_runtime.h>
#include <cuda_bf16.h>

// Problem constants (fixed by the reference: B=4, S=2048, D=2048, K=4)
#define N_ROWS       8192    // B*S
#define N_COLS4      512     // float4 per row (D/4)
#define TPB          256     // half-row per block
#define N_ROWGROUPS  2048
#define ROWS_PER_BLK 4
#define GRID         (2 * N_ROWGROUPS)   // col-half x row-group

__device__ __forceinline__ float fast_ex2(float a) {
    float r;
    asm("ex2.approx.ftz.f32 %0, %1;" : "=f"(r) : "f"(a));
    return r;
}

__global__ void __launch_bounds__(TPB)
gmm_act_kernel(const float4* __restrict__ xin,
               const float*  __restrict__ means,   // (K,2)
               const float*  __restrict__ icov,    // (K,2,2)
               const float4* __restrict__ w4,      // (D/2,K,2): 4 float4 per column
               float4* __restrict__ out)
{
    const int tid = threadIdx.x;
    const int half = blockIdx.x & 1;                 // column half
    const int c    = (half << 8) + tid;              // float4 column 0..511
    const int rb   = blockIdx.x >> 1;                // row-group 0..2047

    // ---- Stage this block's 16KB weight slice through shared memory ----
    // Block needs w4[half*1024 .. half*1024+1024): contiguous -> coalesced.
    __shared__ float4 s_w[1024];
    const int wbase = half << 10;
#pragma unroll
    for (int j = 0; j < 4; j++)
        s_w[tid + 256 * j] = w4[wbase + tid + 256 * j];

    // ---- Expanded quadratic-form coefficients, -0.5*log2(e) folded in ----
    //   log2(pdf_k) = A*x^2 + B*x*y + C*y^2 + D*x + E*y + F
    // Uniform per block; hoisted out of the hot loop by ptxas.
    const float L2E = 1.4426950408889634f;
    float cA[4], cB[4], cC[4], cD[4], cE[4], cF[4];
#pragma unroll
    for (int k = 0; k < 4; k++) {
        const float m0 = means[2 * k + 0];
        const float m1 = means[2 * k + 1];
        const float a  = icov[4 * k + 0];
        const float b  = 0.5f * (icov[4 * k + 1] + icov[4 * k + 2]);
        const float cc = icov[4 * k + 3];
        const float C0 = -0.5f * L2E * a;
        const float C1 = -L2E * b;
        const float C2 = -0.5f * L2E * cc;
        cA[k] = C0;
        cB[k] = C1;
        cC[k] = C2;
        cD[k] = -(2.0f * C0 * m0 + C1 * m1);
        cE[k] = -(C1 * m0 + 2.0f * C2 * m1);
        cF[k] = C0 * m0 * m0 + C1 * m0 * m1 + C2 * m1 * m1;
    }

    __syncthreads();

    // This thread's weights (d0 = 2c, d1 = 2c+1): 4 consecutive float4 in the
    // local slice at 4*tid (one-time LDS, minor phase conflicts only).
    const float4 wa = s_w[4 * tid + 0];  // d0: k0c0 k0c1 k1c0 k1c1
    const float4 wb = s_w[4 * tid + 1];  // d0: k2c0 k2c1 k3c0 k3c1
    const float4 wc = s_w[4 * tid + 2];  // d1: k0c0 k0c1 k1c0 k1c1
    const float4 wd = s_w[4 * tid + 3];  // d1: k2c0 k2c1 k3c0 k3c1
    const float w0c0[4] = {wa.x, wa.z, wb.x, wb.z};
    const float w0c1[4] = {wa.y, wa.w, wb.y, wb.w};
    const float w1c0[4] = {wc.x, wc.z, wd.x, wd.z};
    const float w1c1[4] = {wc.y, wc.w, wd.y, wd.w};

    // Front-batch the 4 row loads (MLP=4). Default caching: x stays
    // L2-resident across graph replays (streaming stores protect it).
    float4 v[ROWS_PER_BLK];
    int    idx[ROWS_PER_BLK];
#pragma unroll
    for (int i = 0; i < ROWS_PER_BLK; i++) {
        idx[i] = (rb + i * N_ROWGROUPS) * N_COLS4 + c;
        v[i]   = xin[idx[i]];
    }

#pragma unroll
    for (int i = 0; i < ROWS_PER_BLK; i++) {
        const float x0 = v[i].x, y0 = v[i].y;
        const float x1 = v[i].z, y1 = v[i].w;

        float r00 = 0.0f, r01 = 0.0f, r10 = 0.0f, r11 = 0.0f;
#pragma unroll
        for (int k = 0; k < 4; k++) {
            // arg = x*(A*x + (B*y + D)) + ((C*y + E)*y + F), depth 3.
            float t0 = fmaf(cA[k], x0, fmaf(cB[k], y0, cD[k]));
            float t1 = fmaf(cA[k], x1, fmaf(cB[k], y1, cD[k]));
            float u0 = fmaf(fmaf(cC[k], y0, cE[k]), y0, cF[k]);
            float u1 = fmaf(fmaf(cC[k], y1, cE[k]), y1, cF[k]);
            const float p0 = fast_ex2(fmaf(x0, t0, u0));
            const float p1 = fast_ex2(fmaf(x1, t1, u1));
            r00 = fmaf(p0, w0c0[k], r00);
            r01 = fmaf(p0, w0c1[k], r01);
            r10 = fmaf(p1, w1c0[k], r10);
            r11 = fmaf(p1, w1c1[k], r11);
        }

        float4 o;
        o.x = x0 * r00;
        o.y = y0 * r01;
        o.z = x1 * r10;
        o.w = y1 * r11;
        // Streaming store: write-once data must not displace x from L2.
        __stcs(&out[idx[i]], o);
    }
}

extern "C" void kernel_launch(void* const* d_in, const int* in_sizes, int n_in,
                              void* d_out, int out_size)
{
    // Inputs identified by element count: x=16777216, means=8, icov=16, w=8192.
    const float* x     = nullptr;
    const float* means = nullptr;
    const float* icov  = nullptr;
    const float* w     = nullptr;
    for (int i = 0; i < n_in; i++) {
        const int n = in_sizes[i];
        if      (n == 16777216) x     = (const float*)d_in[i];
        else if (n == 8)        means = (const float*)d_in[i];
        else if (n == 16)       icov  = (const float*)d_in[i];
        else if (n == 8192)     w     = (const float*)d_in[i];
    }

    gmm_act_kernel<<<GRID, TPB>>>((const float4*)x, means, icov,
                                  (const float4*)w, (float4*)d_out);
}

// round 15
// speedup vs baseline: 1.1492x; 1.1492x over previous
#include <cuda_runtime.h>
#include <cuda_bf16.h>

// Problem constants (fixed by the reference: B=4, S=2048, D=2048, K=4)
#define N_ROWS       8192    // B*S
#define N_COLS4      512     // float4 per row (D/4)
#define TPB          256     // half-row per block
#define N_ROWGROUPS  2048
#define ROWS_PER_BLK 4
#define GRID         (2 * N_ROWGROUPS)   // col-half x row-group

// Scratch (__device__ globals: the sanctioned no-allocation pattern).
__device__ float4 g_wt[2048];   // g_wt[j*512 + c] = w4[4c + j], j in 0..3
__device__ float  g_coef[24];   // cA[0..3] cB[0..3] cC[0..3] cD cE cF

__device__ __forceinline__ float fast_ex2(float a) {
    float r;
    asm("ex2.approx.ftz.f32 %0, %1;" : "=f"(r) : "f"(a));
    return r;
}

// Pre-pass: coalesced-write weight transpose (one-time strided reads over
// 32KB are negligible) + coefficient folding on one thread.
__global__ void prep_kernel(const float4* __restrict__ w4,
                            const float*  __restrict__ means,
                            const float*  __restrict__ icov)
{
    const int i = blockIdx.x * blockDim.x + threadIdx.x;   // 0..2047
    g_wt[i] = w4[4 * (i & 511) + (i >> 9)];

    if (i == 0) {
        // log2(pdf_k) = A*x^2 + B*x*y + C*y^2 + D*x + E*y + F  (-0.5*log2e folded)
        const float L2E = 1.4426950408889634f;
#pragma unroll
        for (int k = 0; k < 4; k++) {
            const float m0 = means[2 * k + 0];
            const float m1 = means[2 * k + 1];
            const float a  = icov[4 * k + 0];
            const float b  = 0.5f * (icov[4 * k + 1] + icov[4 * k + 2]);
            const float cc = icov[4 * k + 3];
            const float C0 = -0.5f * L2E * a;
            const float C1 = -L2E * b;
            const float C2 = -0.5f * L2E * cc;
            g_coef[0  + k] = C0;
            g_coef[4  + k] = C1;
            g_coef[8  + k] = C2;
            g_coef[12 + k] = -(2.0f * C0 * m0 + C1 * m1);
            g_coef[16 + k] = -(C1 * m0 + 2.0f * C2 * m1);
            g_coef[20 + k] = C0 * m0 * m0 + C1 * m0 * m1 + C2 * m1 * m1;
        }
    }
}

__global__ void __launch_bounds__(TPB)
gmm_act_kernel(const float4* __restrict__ xin,
               float4* __restrict__ out)
{
    const int tid = threadIdx.x;
    const int c   = ((blockIdx.x & 1) << 8) + tid;   // float4 column 0..511
    const int rb  = blockIdx.x >> 1;                 // row-group 0..2047

    // Prefolded coefficients (broadcast loads, hoisted out of the hot loop).
    float cA[4], cB[4], cC[4], cD[4], cE[4], cF[4];
#pragma unroll
    for (int k = 0; k < 4; k++) {
        cA[k] = g_coef[0  + k];
        cB[k] = g_coef[4  + k];
        cC[k] = g_coef[8  + k];
        cD[k] = g_coef[12 + k];
        cE[k] = g_coef[16 + k];
        cF[k] = g_coef[20 + k];
    }

    // Weights for this thread's two d-pairs (d0 = 2c, d1 = 2c+1), from the
    // transposed buffer: 4 fully-coalesced LDG.128 (4 L1 wavefronts each).
    const float4 wa = g_wt[       c];   // d0: k0c0 k0c1 k1c0 k1c1
    const float4 wb = g_wt[ 512 + c];   // d0: k2c0 k2c1 k3c0 k3c1
    const float4 wc = g_wt[1024 + c];   // d1: k0c0 k0c1 k1c0 k1c1
    const float4 wd = g_wt[1536 + c];   // d1: k2c0 k2c1 k3c0 k3c1
    const float w0c0[4] = {wa.x, wa.z, wb.x, wb.z};
    const float w0c1[4] = {wa.y, wa.w, wb.y, wb.w};
    const float w1c0[4] = {wc.x, wc.z, wd.x, wd.z};
    const float w1c1[4] = {wc.y, wc.w, wd.y, wd.w};

    // Front-batch the 4 row loads (MLP=4). Default caching: x stays
    // L2-resident across graph replays (streaming stores protect it).
    float4 v[ROWS_PER_BLK];
    int    idx[ROWS_PER_BLK];
#pragma unroll
    for (int i = 0; i < ROWS_PER_BLK; i++) {
        idx[i] = (rb + i * N_ROWGROUPS) * N_COLS4 + c;
        v[i]   = xin[idx[i]];
    }

#pragma unroll
    for (int i = 0; i < ROWS_PER_BLK; i++) {
        const float x0 = v[i].x, y0 = v[i].y;
        const float x1 = v[i].z, y1 = v[i].w;

        float r00 = 0.0f, r01 = 0.0f, r10 = 0.0f, r11 = 0.0f;
#pragma unroll
        for (int k = 0; k < 4; k++) {
            // arg = x*(A*x + (B*y + D)) + ((C*y + E)*y + F), depth 3.
            float t0 = fmaf(cA[k], x0, fmaf(cB[k], y0, cD[k]));
            float t1 = fmaf(cA[k], x1, fmaf(cB[k], y1, cD[k]));
            float u0 = fmaf(fmaf(cC[k], y0, cE[k]), y0, cF[k]);
            float u1 = fmaf(fmaf(cC[k], y1, cE[k]), y1, cF[k]);
            const float p0 = fast_ex2(fmaf(x0, t0, u0));
            const float p1 = fast_ex2(fmaf(x1, t1, u1));
            r00 = fmaf(p0, w0c0[k], r00);
            r01 = fmaf(p0, w0c1[k], r01);
            r10 = fmaf(p1, w1c0[k], r10);
            r11 = fmaf(p1, w1c1[k], r11);
        }

        float4 o;
        o.x = x0 * r00;
        o.y = y0 * r01;
        o.z = x1 * r10;
        o.w = y1 * r11;
        // Streaming store: write-once data must not displace x from L2.
        __stcs(&out[idx[i]], o);
    }
}

extern "C" void kernel_launch(void* const* d_in, const int* in_sizes, int n_in,
                              void* d_out, int out_size)
{
    // Inputs identified by element count: x=16777216, means=8, icov=16, w=8192.
    const float* x     = nullptr;
    const float* means = nullptr;
    const float* icov  = nullptr;
    const float* w     = nullptr;
    for (int i = 0; i < n_in; i++) {
        const int n = in_sizes[i];
        if      (n == 16777216) x     = (const float*)d_in[i];
        else if (n == 8)        means = (const float*)d_in[i];
        else if (n == 16)       icov  = (const float*)d_in[i];
        else if (n == 8192)     w     = (const float*)d_in[i];
    }

    prep_kernel<<<4, 512>>>((const float4*)w, means, icov);
    gmm_act_kernel<<<GRID, TPB>>>((const float4*)x, (float4*)d_out);
}